// round 3
// baseline (speedup 1.0000x reference)
#include <cuda_runtime.h>
#include <cstdint>

// Sparse embedding-bag: out[b,:] = bias + sum_k weight[ft_ics[b,k],:] * ft_vals[b,k]
// B=16384, K=32, N_OUT=256. Table 41024x256 fp32 = 42 MB (L2-resident).
//
// R3 design: warp = one batch row; lane tx owns 8 contiguous output floats
// [8*tx, 8*tx+8). Weight gathers use 256-bit LDG (ld.global.nc.L2::evict_last
// .v8.b32) -> one instruction per thread per feature, warp reads the full
// 1 KB row coalesced. k-loop unrolled x4 with loads front-batched -> 4
// independent 32B loads (128 B) in flight per thread. Branchless padding.

#define K_FEATS 32
#define ROWS_PER_BLOCK 8
#define KU 4  // k unroll

struct f8 { float4 a, b; };

__device__ __forceinline__ f8 ldg256_el(const float* p) {
    unsigned r0, r1, r2, r3, r4, r5, r6, r7;
    asm volatile(
        "ld.global.nc.L2::evict_last.v8.b32 {%0,%1,%2,%3,%4,%5,%6,%7}, [%8];"
        : "=r"(r0), "=r"(r1), "=r"(r2), "=r"(r3),
          "=r"(r4), "=r"(r5), "=r"(r6), "=r"(r7)
        : "l"(p));
    f8 v;
    v.a.x = __uint_as_float(r0); v.a.y = __uint_as_float(r1);
    v.a.z = __uint_as_float(r2); v.a.w = __uint_as_float(r3);
    v.b.x = __uint_as_float(r4); v.b.y = __uint_as_float(r5);
    v.b.z = __uint_as_float(r6); v.b.w = __uint_as_float(r7);
    return v;
}

__global__ __launch_bounds__(32 * ROWS_PER_BLOCK, 4)
void ft_embed_bag_kernel(const int* __restrict__ ics,
                         const float* __restrict__ vals,
                         const float* __restrict__ weight,    // [N_IN][256]
                         const float4* __restrict__ bias,     // [64] float4
                         float4* __restrict__ out)            // [B][64] float4
{
    __shared__ int   s_idx[ROWS_PER_BLOCK][K_FEATS];
    __shared__ float s_val[ROWS_PER_BLOCK][K_FEATS];

    const int ty = threadIdx.y;            // batch row within block
    const int tx = threadIdx.x;            // lane: floats [8*tx, 8*tx+8)
    const int b  = blockIdx.x * ROWS_PER_BLOCK + ty;

    // Stage indices + values (one thread per (row, feat)), branchless mask.
    {
        const int   raw = __ldg(&ics[b * K_FEATS + tx]);
        const float v   = __ldg(&vals[b * K_FEATS + tx]);
        const bool valid = (raw >= 0);
        s_idx[ty][tx] = valid ? raw : 0;
        s_val[ty][tx] = valid ? v : 0.0f;
    }
    __syncthreads();

    float4 acc0 = bias[tx * 2];
    float4 acc1 = bias[tx * 2 + 1];

    #pragma unroll
    for (int k0 = 0; k0 < K_FEATS; k0 += KU) {
        int   idx[KU];
        float v[KU];
        #pragma unroll
        for (int j = 0; j < KU; ++j) {
            idx[j] = s_idx[ty][k0 + j];
            v[j]   = s_val[ty][k0 + j];
        }

        // Front-batch KU independent 256-bit loads.
        f8 w[KU];
        #pragma unroll
        for (int j = 0; j < KU; ++j)
            w[j] = ldg256_el(weight + (size_t)idx[j] * 256 + tx * 8);

        #pragma unroll
        for (int j = 0; j < KU; ++j) {
            acc0.x = fmaf(v[j], w[j].a.x, acc0.x);
            acc0.y = fmaf(v[j], w[j].a.y, acc0.y);
            acc0.z = fmaf(v[j], w[j].a.z, acc0.z);
            acc0.w = fmaf(v[j], w[j].a.w, acc0.w);
            acc1.x = fmaf(v[j], w[j].b.x, acc1.x);
            acc1.y = fmaf(v[j], w[j].b.y, acc1.y);
            acc1.z = fmaf(v[j], w[j].b.z, acc1.z);
            acc1.w = fmaf(v[j], w[j].b.w, acc1.w);
        }
    }

    // Streaming stores: single-use output, keep it out of the table's L2 space.
    __stcs(&out[(size_t)b * 64 + tx * 2],     acc0);
    __stcs(&out[(size_t)b * 64 + tx * 2 + 1], acc1);
}

extern "C" void kernel_launch(void* const* d_in, const int* in_sizes, int n_in,
                              void* d_out, int out_size)
{
    const int*    ics    = (const int*)d_in[0];
    const float*  vals   = (const float*)d_in[1];
    const float*  weight = (const float*)d_in[2];
    const float4* bias   = (const float4*)d_in[3];
    float4*       out    = (float4*)d_out;

    const int B = in_sizes[0] / K_FEATS;  // 16384

    dim3 block(32, ROWS_PER_BLOCK);
    dim3 grid(B / ROWS_PER_BLOCK);
    ft_embed_bag_kernel<<<grid, block>>>(ics, vals, weight, bias, out);
}

// round 4
// speedup vs baseline: 1.0224x; 1.0224x over previous
#include <cuda_runtime.h>
#include <cstdint>

// Sparse embedding-bag: out[b,:] = bias + sum_k weight[ft_ics[b,k],:] * ft_vals[b,k]
// B=16384, K=32, N_OUT=256. Table 41024x256 fp32 = 42 MB (L2-resident).
//
// R4: gathers shattered into warp-coalesced LDG.32 (1 wavefront per LDG ->
// 1.0 cyc/wf cross-LDG rate instead of 2.07 cyc/wf within-LDG replays that
// bound R1/R3 at ~33.5us). Warp = one batch row; lane tx owns columns
// {c*32+tx : c=0..7}; 8 scalar accumulators. KU=2 features front-batched ->
// 16 independent LDG.32 in flight per thread.

#define K_FEATS 32
#define ROWS_PER_BLOCK 8
#define KU 2

__global__ __launch_bounds__(32 * ROWS_PER_BLOCK, 5)
void ft_embed_bag_kernel(const int* __restrict__ ics,
                         const float* __restrict__ vals,
                         const float* __restrict__ weight,   // [N_IN][256]
                         const float* __restrict__ bias,     // [256]
                         float* __restrict__ out)            // [B][256]
{
    __shared__ int   s_idx[ROWS_PER_BLOCK][K_FEATS];
    __shared__ float s_val[ROWS_PER_BLOCK][K_FEATS];

    const int ty = threadIdx.y;          // batch row within block (one warp)
    const int tx = threadIdx.x;          // lane
    const int b  = blockIdx.x * ROWS_PER_BLOCK + ty;

    // Stage this row's 32 indices/values; branchless padding mask.
    {
        const int   raw = __ldg(&ics[b * K_FEATS + tx]);
        const float v   = __ldg(&vals[b * K_FEATS + tx]);
        const bool valid = (raw >= 0);
        s_idx[ty][tx] = valid ? raw : 0;
        s_val[ty][tx] = valid ? v : 0.0f;
    }
    __syncwarp();

    float acc[8];
    #pragma unroll
    for (int c = 0; c < 8; ++c)
        acc[c] = __ldg(&bias[c * 32 + tx]);

    #pragma unroll
    for (int k0 = 0; k0 < K_FEATS; k0 += KU) {
        int   idx[KU];
        float v[KU];
        #pragma unroll
        for (int j = 0; j < KU; ++j) {
            idx[j] = s_idx[ty][k0 + j];
            v[j]   = s_val[ty][k0 + j];
        }

        // Front-batch 8*KU independent coalesced LDG.32 (1 line each).
        float w[KU][8];
        #pragma unroll
        for (int j = 0; j < KU; ++j) {
            const float* base = weight + (size_t)idx[j] * 256 + tx;
            #pragma unroll
            for (int c = 0; c < 8; ++c)
                w[j][c] = __ldg(base + c * 32);
        }

        #pragma unroll
        for (int j = 0; j < KU; ++j)
            #pragma unroll
            for (int c = 0; c < 8; ++c)
                acc[c] = fmaf(v[j], w[j][c], acc[c]);
    }

    // Coalesced streaming stores (single-use output).
    float* orow = out + (size_t)b * 256 + tx;
    #pragma unroll
    for (int c = 0; c < 8; ++c)
        __stcs(orow + c * 32, acc[c]);
}

extern "C" void kernel_launch(void* const* d_in, const int* in_sizes, int n_in,
                              void* d_out, int out_size)
{
    const int*   ics    = (const int*)d_in[0];
    const float* vals   = (const float*)d_in[1];
    const float* weight = (const float*)d_in[2];
    const float* bias   = (const float*)d_in[3];
    float*       out    = (float*)d_out;

    const int B = in_sizes[0] / K_FEATS;  // 16384

    dim3 block(32, ROWS_PER_BLOCK);
    dim3 grid(B / ROWS_PER_BLOCK);
    ft_embed_bag_kernel<<<grid, block>>>(ics, vals, weight, bias, out);
}

// round 5
// speedup vs baseline: 1.1632x; 1.1376x over previous
#include <cuda_runtime.h>
#include <cuda_fp16.h>
#include <cstdint>

// Sparse embedding-bag: out[b,:] = bias + sum_k weight[ft_ics[b,k],:] * ft_vals[b,k]
// B=16384, K=32, N_OUT=256. Table 41024x256 fp32 = 42 MB.
//
// R5: evidence from R1/R3/R4 (three different load shapes, all ~33us, L2 58-66%
// busiest) says random-gather L2 bandwidth (~2/3 of LTS streaming cap) is the
// wall. So halve the bytes: pre-pass converts the table to fp16 (21 MB
// __device__ scratch; fp32+fp16 tables both stay L2-resident across graph
// replays), gather kernel reads 512 B/row instead of 1 KB. fp32 accumulation;
// fp16 rounding ~2.4e-4 rel, threshold 1e-3.

#define N_IN_ROWS 41024
#define N_OUT_COLS 256
#define K_FEATS 32
#define ROWS_PER_BLOCK 8
#define KU 4

__device__ __half g_w16[(size_t)N_IN_ROWS * N_OUT_COLS];

// ---------------- conversion: fp32 table -> fp16 table (streaming) ----------
__global__ __launch_bounds__(256)
void convert_w16_kernel(const float4* __restrict__ w32)  // [N_IN*256/4] float4
{
    const size_t n4 = (size_t)N_IN_ROWS * N_OUT_COLS / 4;
    uint2* dst = reinterpret_cast<uint2*>(g_w16);
    for (size_t i = (size_t)blockIdx.x * blockDim.x + threadIdx.x;
         i < n4; i += (size_t)gridDim.x * blockDim.x) {
        const float4 w = __ldg(&w32[i]);
        __half2 h0 = __floats2half2_rn(w.x, w.y);
        __half2 h1 = __floats2half2_rn(w.z, w.w);
        uint2 u;
        u.x = *reinterpret_cast<unsigned*>(&h0);
        u.y = *reinterpret_cast<unsigned*>(&h1);
        dst[i] = u;
    }
}

// ---------------- gather: fp16 table, fp32 accumulate -----------------------
// Warp = one batch row. Lane tx owns column pairs {c*64 + 2*tx, +1 : c=0..3}.
// Each feature row = 128 half2; a warp covers it with 4 coalesced LDG.32
// (1 x 128B line each). KU=4 features front-batched -> 16 loads in flight.
__global__ __launch_bounds__(32 * ROWS_PER_BLOCK, 6)
void ft_embed_bag_kernel(const int* __restrict__ ics,
                         const float* __restrict__ vals,
                         const float* __restrict__ bias,   // [256]
                         float* __restrict__ out)          // [B][256]
{
    __shared__ int   s_idx[ROWS_PER_BLOCK][K_FEATS];
    __shared__ float s_val[ROWS_PER_BLOCK][K_FEATS];

    const int ty = threadIdx.y;
    const int tx = threadIdx.x;
    const int b  = blockIdx.x * ROWS_PER_BLOCK + ty;

    {
        const int   raw = __ldg(&ics[b * K_FEATS + tx]);
        const float v   = __ldg(&vals[b * K_FEATS + tx]);
        const bool valid = (raw >= 0);
        s_idx[ty][tx] = valid ? raw : 0;
        s_val[ty][tx] = valid ? v : 0.0f;
    }
    __syncwarp();

    // acc[2c], acc[2c+1] = output cols c*64 + 2tx, c*64 + 2tx + 1
    float acc[8];
    #pragma unroll
    for (int c = 0; c < 4; ++c) {
        acc[2 * c]     = __ldg(&bias[c * 64 + 2 * tx]);
        acc[2 * c + 1] = __ldg(&bias[c * 64 + 2 * tx + 1]);
    }

    const __half2* wtab = reinterpret_cast<const __half2*>(g_w16);

    #pragma unroll
    for (int k0 = 0; k0 < K_FEATS; k0 += KU) {
        int   idx[KU];
        float v[KU];
        #pragma unroll
        for (int j = 0; j < KU; ++j) {
            idx[j] = s_idx[ty][k0 + j];
            v[j]   = s_val[ty][k0 + j];
        }

        // Front-batch 4*KU independent coalesced LDG.32 (one 128B line each).
        __half2 w[KU][4];
        #pragma unroll
        for (int j = 0; j < KU; ++j) {
            const __half2* base = wtab + (size_t)idx[j] * 128 + tx;
            #pragma unroll
            for (int c = 0; c < 4; ++c)
                w[j][c] = __ldg(base + c * 32);
        }

        #pragma unroll
        for (int j = 0; j < KU; ++j) {
            #pragma unroll
            for (int c = 0; c < 4; ++c) {
                const float2 wf = __half22float2(w[j][c]);
                acc[2 * c]     = fmaf(v[j], wf.x, acc[2 * c]);
                acc[2 * c + 1] = fmaf(v[j], wf.y, acc[2 * c + 1]);
            }
        }
    }

    // Streaming float2 stores (single-use output).
    float* orow = out + (size_t)b * N_OUT_COLS;
    #pragma unroll
    for (int c = 0; c < 4; ++c) {
        float2 o = make_float2(acc[2 * c], acc[2 * c + 1]);
        __stcs(reinterpret_cast<float2*>(orow + c * 64) + tx, o);
    }
}

extern "C" void kernel_launch(void* const* d_in, const int* in_sizes, int n_in,
                              void* d_out, int out_size)
{
    const int*   ics    = (const int*)d_in[0];
    const float* vals   = (const float*)d_in[1];
    const float* weight = (const float*)d_in[2];
    const float* bias   = (const float*)d_in[3];
    float*       out    = (float*)d_out;

    const int B = in_sizes[0] / K_FEATS;  // 16384

    // Pass 1: fp32 -> fp16 table (streaming, L2-resident across replays).
    convert_w16_kernel<<<2048, 256>>>((const float4*)weight);

    // Pass 2: gather/accumulate from fp16 table.
    dim3 block(32, ROWS_PER_BLOCK);
    dim3 grid(B / ROWS_PER_BLOCK);
    ft_embed_bag_kernel<<<grid, block>>>(ics, vals, bias, out);
}